// round 14
// baseline (speedup 1.0000x reference)
#include <cuda_runtime.h>
#include <cuda_fp16.h>
#include <cstdint>

#define B_ 16
#define L_ 680
#define C_ 1024
#define H_ 16
#define D_ 64
#define NSEG 10
#define M_TOK (B_*L_)          // 10880
#define SUMSQ 110468
#define LN100 4.605170185988091f

// ---------------- scratch -------------------------------------------------
__device__ float  g_qkv[(size_t)M_TOK * 3 * C_];
__device__ float  g_att[(size_t)M_TOK * C_];
__device__ float  g_vt [(size_t)B_ * H_ * D_ * L_];
__device__ float  g_S  [(size_t)B_ * H_ * SUMSQ];
__device__ float  g_bias[3 * C_];
__device__ __half g_xh [(size_t)M_TOK * C_];
__device__ __half g_wh [(size_t)3 * C_ * C_];
__device__ __half g_ah [(size_t)M_TOK * C_];
__device__ __half g_ph [(size_t)C_ * C_];

// ---------------- helpers --------------------------------------------------
__device__ __forceinline__ void mma16h(float* c, const uint32_t* a, const uint32_t* b) {
    asm volatile(
        "mma.sync.aligned.m16n8k16.row.col.f32.f16.f16.f32 "
        "{%0,%1,%2,%3}, {%4,%5,%6,%7}, {%8,%9}, {%0,%1,%2,%3};\n"
        : "+f"(c[0]), "+f"(c[1]), "+f"(c[2]), "+f"(c[3])
        : "r"(a[0]), "r"(a[1]), "r"(a[2]), "r"(a[3]), "r"(b[0]), "r"(b[1]));
}

__device__ __forceinline__ uint32_t smem_u32(const void* p) {
    return (uint32_t)__cvta_generic_to_shared(p);
}

__device__ __forceinline__ void cp16(uint32_t s, const void* g) {
    asm volatile("cp.async.cg.shared.global [%0], [%1], 16;\n" :: "r"(s), "l"(g));
}

__device__ __forceinline__ uint4 pack8h(float4 v0, float4 v1) {
    __half2 h0 = __floats2half2_rn(v0.x, v0.y);
    __half2 h1 = __floats2half2_rn(v0.z, v0.w);
    __half2 h2 = __floats2half2_rn(v1.x, v1.y);
    __half2 h3 = __floats2half2_rn(v1.z, v1.w);
    uint4 u;
    u.x = *(uint32_t*)&h0; u.y = *(uint32_t*)&h1;
    u.z = *(uint32_t*)&h2; u.w = *(uint32_t*)&h3;
    return u;
}

// ---------------- fp32 -> fp16 convert ------------------------------------
__global__ void f2h_kernel(const float* __restrict__ src, __half* __restrict__ dst,
                           int n4) {
    int i = blockIdx.x * blockDim.x + threadIdx.x;
    if (i >= n4) return;
    float4 v = *(const float4*)(src + (size_t)i * 4);
    __half2 lo = __floats2half2_rn(v.x, v.y);
    __half2 hi = __floats2half2_rn(v.z, v.w);
    *(__half2*)(dst + (size_t)i * 4)     = lo;
    *(__half2*)(dst + (size_t)i * 4 + 2) = hi;
}

// ---------------- bias assembly -------------------------------------------
__global__ void build_bias(const float* __restrict__ qb, const float* __restrict__ vb) {
    int j = blockIdx.x * blockDim.x + threadIdx.x;
    if (j >= 3 * C_) return;
    float v = 0.0f;
    if (j < C_) v = qb[j];
    else if (j >= 2 * C_) v = vb[j - 2 * C_];
    g_bias[j] = v;
}

// ========= cp.async fp16 GEMM: CTA 128x128, 4 warps of 64x64, 2 CTAs/SM ====
#define SROWH 56
#define BUFH (128 * SROWH)
__global__ __launch_bounds__(128, 2) void gemm_h(
    const __half* __restrict__ A, const __half* __restrict__ Bm,
    const float* __restrict__ bias, float* __restrict__ Cmat,
    int M, int N, int K)
{
    extern __shared__ __half smh[];

    const int tid  = threadIdx.x;
    const int lane = tid & 31, warp = tid >> 5;
    const int wm = warp & 1, wn = warp >> 1;
    const int qr = lane >> 2, qc = lane & 3;
    const int bm = blockIdx.x * 128, bn = blockIdx.y * 128;

    const int rr0 = tid >> 2;
    const int ch  = (tid & 3) << 3;

    float acc[4][8][4];
#pragma unroll
    for (int i = 0; i < 4; i++)
#pragma unroll
        for (int j = 0; j < 8; j++)
#pragma unroll
            for (int e = 0; e < 4; e++) acc[i][j][e] = 0.0f;

    const int nk = K >> 5;

    {
        __half* As = smh;
        __half* Bs = smh + BUFH;
#pragma unroll
        for (int i = 0; i < 4; i++) {
            int r = rr0 + 32 * i;
            cp16(smem_u32(As + r * SROWH + ch), A  + (size_t)(bm + r) * K + ch);
            cp16(smem_u32(Bs + r * SROWH + ch), Bm + (size_t)(bn + r) * K + ch);
        }
        asm volatile("cp.async.commit_group;\n");
    }

    for (int kt = 0; kt < nk; kt++) {
        asm volatile("cp.async.wait_group 0;\n");
        __syncthreads();

        if (kt + 1 < nk) {
            __half* As = smh + ((kt + 1) & 1) * 2 * BUFH;
            __half* Bs = As + BUFH;
            int ko = (kt + 1) << 5;
#pragma unroll
            for (int i = 0; i < 4; i++) {
                int r = rr0 + 32 * i;
                cp16(smem_u32(As + r * SROWH + ch), A  + (size_t)(bm + r) * K + ko + ch);
                cp16(smem_u32(Bs + r * SROWH + ch), Bm + (size_t)(bn + r) * K + ko + ch);
            }
            asm volatile("cp.async.commit_group;\n");
        }

        const __half* As = smh + (kt & 1) * 2 * BUFH;
        const __half* Bs = As + BUFH;

#pragma unroll
        for (int ks = 0; ks < 2; ks++) {
            const int cb = ks * 16 + qc * 2;
            uint32_t a[4][4], b[8][2];
#pragma unroll
            for (int mt = 0; mt < 4; mt++) {
                int row = wm * 64 + mt * 16 + qr;
                a[mt][0] = *(const uint32_t*)&As[row * SROWH + cb];
                a[mt][1] = *(const uint32_t*)&As[(row + 8) * SROWH + cb];
                a[mt][2] = *(const uint32_t*)&As[row * SROWH + cb + 8];
                a[mt][3] = *(const uint32_t*)&As[(row + 8) * SROWH + cb + 8];
            }
#pragma unroll
            for (int nt = 0; nt < 8; nt++) {
                int row = wn * 64 + nt * 8 + qr;
                b[nt][0] = *(const uint32_t*)&Bs[row * SROWH + cb];
                b[nt][1] = *(const uint32_t*)&Bs[row * SROWH + cb + 8];
            }
#pragma unroll
            for (int mt = 0; mt < 4; mt++)
#pragma unroll
                for (int nt = 0; nt < 8; nt++)
                    mma16h(acc[mt][nt], a[mt], b[nt]);
        }
        __syncthreads();
    }

#pragma unroll
    for (int mt = 0; mt < 4; mt++)
#pragma unroll
        for (int nt = 0; nt < 8; nt++) {
            int r = bm + wm * 64 + mt * 16 + qr;
            int c0 = bn + wn * 64 + nt * 8 + qc * 2;
            float b0 = bias[c0], b1 = bias[c0 + 1];
            Cmat[(size_t)r * N + c0]           = acc[mt][nt][0] + b0;
            Cmat[(size_t)r * N + c0 + 1]       = acc[mt][nt][1] + b1;
            Cmat[(size_t)(r + 8) * N + c0]     = acc[mt][nt][2] + b0;
            Cmat[(size_t)(r + 8) * N + c0 + 1] = acc[mt][nt][3] + b1;
        }
}

// ---------------- l2 normalize q (with scale) and k ------------------------
__global__ void normalize_qk(const float* __restrict__ scale_log) {
    int w = (blockIdx.x * blockDim.x + threadIdx.x) >> 5;
    int lane = threadIdx.x & 31;
    if (w >= M_TOK * H_) return;
    int t = w >> 4, h = w & 15;
    float sc = __expf(fminf(scale_log[h], LN100));

    float* q = g_qkv + ((size_t)t * 3 + 0) * C_ + h * D_;
    float* k = g_qkv + ((size_t)t * 3 + 1) * C_ + h * D_;

    float q0 = q[lane], q1 = q[lane + 32];
    float s = q0 * q0 + q1 * q1;
#pragma unroll
    for (int o = 16; o; o >>= 1) s += __shfl_xor_sync(~0u, s, o);
    float inv = sc / fmaxf(sqrtf(s), 1e-12f);
    q[lane] = q0 * inv; q[lane + 32] = q1 * inv;

    float k0 = k[lane], k1 = k[lane + 32];
    float sk = k0 * k0 + k1 * k1;
#pragma unroll
    for (int o = 16; o; o >>= 1) sk += __shfl_xor_sync(~0u, sk, o);
    float invk = 1.0f / fmaxf(sqrtf(sk), 1e-12f);
    k[lane] = k0 * invk; k[lane + 32] = k1 * invk;
}

// ---------------- V transpose ----------------------------------------------
__global__ void transpose_v() {
    __shared__ float tile[32][65];
    int bh = blockIdx.x;
    int l0 = blockIdx.y * 32;
    int b = bh >> 4, h = bh & 15;
    int tid = threadIdx.x;

    int d = tid & 63, lo = tid >> 6;
#pragma unroll
    for (int p = 0; p < 8; p++) {
        int l = l0 + p * 4 + lo;
        if (l < L_)
            tile[p * 4 + lo][d] = g_qkv[(((size_t)b * L_ + l) * 3 + 2) * C_ + h * D_ + d];
    }
    __syncthreads();

    int ll = tid & 31, d0 = tid >> 5;
#pragma unroll
    for (int p = 0; p < 8; p++) {
        int d2 = p * 8 + d0;
        int l = l0 + ll;
        if (l < L_)
            g_vt[((size_t)bh * D_ + d2) * L_ + l] = tile[ll][d2];
    }
}

// ---------------- S = Q @ K^T per (bh, segment), fp16 mma -------------------
// dyn smem: Ks half[256][72] (36864B) + Qs half[64][72] (9216B) = 46080 B
__global__ __launch_bounds__(256) void attn_s(const int* __restrict__ pn) {
    extern __shared__ __half smha[];
    __half (*Ks)[72] = (__half(*)[72])smha;
    __half (*Qs)[72] = (__half(*)[72])(smha + 256 * 72);

    int bh = blockIdx.x, seg = blockIdx.y;
    int b = bh >> 4, h = bh & 15;
    int start = 0, sqb = 0, ln = 0;
    for (int s = 0; s < NSEG; s++) {
        int p = pn[s];
        if (s == seg) { ln = p; break; }
        start += p; sqb += p * p;
    }
    int tid = threadIdx.x, lane = tid & 31, warp = tid >> 5;
    int qr = lane >> 2, qc = lane & 3;
    int nk = (ln + 7) & ~7;

    const float* Kg = g_qkv + (((size_t)b * L_ + start) * 3 + 1) * C_ + h * D_;
    for (int f = tid; f < nk * 8; f += 256) {
        int r = f >> 3, c8 = (f & 7) << 3;
        if (r < ln) {
            const float* p = Kg + (size_t)r * 3 * C_ + c8;
            *(uint4*)&Ks[r][c8] = pack8h(*(const float4*)p, *(const float4*)(p + 4));
        } else {
            *(uint4*)&Ks[r][c8] = make_uint4(0, 0, 0, 0);
        }
    }

    const float* Qg = g_qkv + (((size_t)b * L_ + start) * 3 + 0) * C_ + h * D_;
    float* Sg = g_S + (size_t)bh * SUMSQ + sqb;
    int Ntile = nk >> 3;

    for (int m0 = 0; m0 < ln; m0 += 64) {
        __syncthreads();
        int prows = min(64, (ln - m0 + 15) & ~15);
        for (int f = tid; f < prows * 8; f += 256) {
            int r = f >> 3, c8 = (f & 7) << 3;
            int gi = m0 + r;
            if (gi < ln) {
                const float* p = Qg + (size_t)gi * 3 * C_ + c8;
                *(uint4*)&Qs[r][c8] = pack8h(*(const float4*)p, *(const float4*)(p + 4));
            } else {
                *(uint4*)&Qs[r][c8] = make_uint4(0, 0, 0, 0);
            }
        }
        __syncthreads();

        int Mtile = prows >> 4;
        for (int t = warp; t < Mtile * Ntile; t += 8) {
            int mi = t / Ntile, ni = t % Ntile;
            float acc[4] = {0.f, 0.f, 0.f, 0.f};
            int row = mi * 16 + qr;
            int jr = ni * 8 + qr;
#pragma unroll
            for (int ks = 0; ks < 4; ks++) {            // 4 k16 steps over D=64
                const int cb = ks * 16 + qc * 2;
                uint32_t a[4], bf[2];
                a[0] = *(const uint32_t*)&Qs[row][cb];
                a[1] = *(const uint32_t*)&Qs[row + 8][cb];
                a[2] = *(const uint32_t*)&Qs[row][cb + 8];
                a[3] = *(const uint32_t*)&Qs[row + 8][cb + 8];
                bf[0] = *(const uint32_t*)&Ks[jr][cb];
                bf[1] = *(const uint32_t*)&Ks[jr][cb + 8];
                mma16h(acc, a, bf);
            }
            int i0 = m0 + row;
            int j0 = ni * 8 + qc * 2;
            if (i0 < ln) {
                if (j0 < ln)     Sg[(size_t)i0 * ln + j0]     = acc[0];
                if (j0 + 1 < ln) Sg[(size_t)i0 * ln + j0 + 1] = acc[1];
            }
            if (i0 + 8 < ln) {
                if (j0 < ln)     Sg[(size_t)(i0 + 8) * ln + j0]     = acc[2];
                if (j0 + 1 < ln) Sg[(size_t)(i0 + 8) * ln + j0 + 1] = acc[3];
            }
        }
    }
}

// ---------- O = softmax(S) @ V, softmax fused, fp16 mma --------------------
// dyn smem: Vt half[64][264] (33792B) + Ps u32[32][260] (33280B)
//           + Ph half[32][264] (16896B) = 83968 B  (2 CTAs/SM)
__global__ __launch_bounds__(256) void attn_o(const int* __restrict__ pn) {
    extern __shared__ char smo[];
    __half   (*Vt)[264] = (__half(*)[264])smo;
    uint32_t (*Ps)[260] = (uint32_t(*)[260])(smo + 33792);
    __half   (*Ph)[264] = (__half(*)[264])(smo + 33792 + 33280);

    int bh = blockIdx.x, seg = blockIdx.y;
    int b = bh >> 4, h = bh & 15;
    int start = 0, sqb = 0, ln = 0;
    for (int s = 0; s < NSEG; s++) {
        int p = pn[s];
        if (s == seg) { ln = p; break; }
        start += p; sqb += p * p;
    }
    int tid = threadIdx.x, lane = tid & 31, warp = tid >> 5;
    int qr = lane >> 2, qc = lane & 3;
    int nk16 = (ln + 15) & ~15;
    int Ksteps = nk16 >> 4;

    const float* Vg = g_vt + (size_t)bh * D_ * L_;
    for (int f = tid; f < 64 * nk16; f += 256) {
        int d = f / nk16, j = f % nk16;
        Vt[d][j] = (j < ln) ? __float2half(Vg[(size_t)d * L_ + start + j])
                            : __half(0.0f);
    }

    const float* Sg = g_S + (size_t)bh * SUMSQ + sqb;

    for (int m0 = 0; m0 < ln; m0 += 32) {
        __syncthreads();
        int prows = min(32, (ln - m0 + 15) & ~15);
        for (int f = tid; f < prows * nk16; f += 256) {
            int r = f / nk16, j = f % nk16;
            int gi = m0 + r;
            Ps[r][j < 260 ? j : 259] = (gi < ln && j < ln)
                       ? __float_as_uint(Sg[(size_t)gi * ln + j]) : 0u;
        }
        __syncthreads();

        // softmax (fp32) -> fp16 P panel
        for (int rr = warp; rr < prows; rr += 8) {
            float v[8];
            int cnt = 0;
            float m = -3.4e38f;
            for (int j = lane; j < ln; j += 32) {
                v[cnt] = __uint_as_float(Ps[rr][j]);
                m = fmaxf(m, v[cnt]); cnt++;
            }
#pragma unroll
            for (int o = 16; o; o >>= 1) m = fmaxf(m, __shfl_xor_sync(~0u, m, o));
            float s = 0.0f;
            for (int u = 0; u < cnt; u++) { v[u] = __expf(v[u] - m); s += v[u]; }
#pragma unroll
            for (int o = 16; o; o >>= 1) s += __shfl_xor_sync(~0u, s, o);
            float inv = 1.0f / s;
            cnt = 0;
            for (int j = lane; j < ln; j += 32) {
                Ph[rr][j] = __float2half(v[cnt] * inv); cnt++;
            }
            for (int j = ln + lane; j < nk16; j += 32)
                Ph[rr][j] = __half(0.0f);
        }
        __syncthreads();

        int Mtile = prows >> 4;
        for (int t = warp; t < Mtile * 8; t += 8) {
            int mi = t >> 3, ni = t & 7;
            float acc[4] = {0.f, 0.f, 0.f, 0.f};
            int row = mi * 16 + qr;
            int dr = ni * 8 + qr;
            for (int ks = 0; ks < Ksteps; ks++) {
                const int cb = ks * 16 + qc * 2;
                uint32_t a[4], bf[2];
                a[0] = *(const uint32_t*)&Ph[row][cb];
                a[1] = *(const uint32_t*)&Ph[row + 8][cb];
                a[2] = *(const uint32_t*)&Ph[row][cb + 8];
                a[3] = *(const uint32_t*)&Ph[row + 8][cb + 8];
                bf[0] = *(const uint32_t*)&Vt[dr][cb];
                bf[1] = *(const uint32_t*)&Vt[dr][cb + 8];
                mma16h(acc, a, bf);
            }
            int i0 = m0 + row;
            int c0 = ni * 8 + qc * 2;
            if (i0 < ln) {
                size_t o = ((size_t)b * L_ + start + i0) * C_ + h * D_ + c0;
                g_att[o] = acc[0]; g_att[o + 1] = acc[1];
            }
            if (i0 + 8 < ln) {
                size_t o = ((size_t)b * L_ + start + i0 + 8) * C_ + h * D_ + c0;
                g_att[o] = acc[2]; g_att[o + 1] = acc[3];
            }
        }
    }
}

// ---------------- launch ---------------------------------------------------
extern "C" void kernel_launch(void* const* d_in, const int* in_sizes, int n_in,
                              void* d_out, int out_size) {
    const float* x    = (const float*)d_in[0];
    const int*   pn   = (const int*)  d_in[1];
    const float* wqkv = (const float*)d_in[2];
    const float* qb   = (const float*)d_in[3];
    const float* vb   = (const float*)d_in[4];
    const float* slog = (const float*)d_in[5];
    const float* pw   = (const float*)d_in[6];
    const float* pb   = (const float*)d_in[7];
    float* out = (float*)d_out;

    float *p_qkv, *p_att, *p_bias;
    __half *p_xh, *p_wh, *p_ah, *p_ph;
    cudaGetSymbolAddress((void**)&p_qkv,  g_qkv);
    cudaGetSymbolAddress((void**)&p_att,  g_att);
    cudaGetSymbolAddress((void**)&p_bias, g_bias);
    cudaGetSymbolAddress((void**)&p_xh,   g_xh);
    cudaGetSymbolAddress((void**)&p_wh,   g_wh);
    cudaGetSymbolAddress((void**)&p_ah,   g_ah);
    cudaGetSymbolAddress((void**)&p_ph,   g_ph);

    cudaFuncSetAttribute(gemm_h, cudaFuncAttributeMaxDynamicSharedMemorySize, 57344);
    cudaFuncSetAttribute(attn_s, cudaFuncAttributeMaxDynamicSharedMemorySize, 46080);
    cudaFuncSetAttribute(attn_o, cudaFuncAttributeMaxDynamicSharedMemorySize, 83968);

    const int nx4 = M_TOK * C_ / 4, nw4 = 3 * C_ * C_ / 4, np4 = C_ * C_ / 4;

    build_bias<<<12, 256>>>(qb, vb);
    f2h_kernel<<<(nx4 + 255) / 256, 256>>>(x, p_xh, nx4);
    f2h_kernel<<<(nw4 + 255) / 256, 256>>>(wqkv, p_wh, nw4);
    gemm_h<<<dim3(M_TOK / 128, (3 * C_) / 128), 128, 57344>>>(p_xh, p_wh, p_bias,
                                                              p_qkv, M_TOK, 3 * C_, C_);
    normalize_qk<<<(M_TOK * H_) / 8, 256>>>(slog);
    transpose_v<<<dim3(B_ * H_, (L_ + 31) / 32), 256>>>();
    attn_s<<<dim3(B_ * H_, NSEG), 256, 46080>>>(pn);
    attn_o<<<dim3(B_ * H_, NSEG), 256, 83968>>>(pn);
    f2h_kernel<<<(nx4 + 255) / 256, 256>>>(p_att, p_ah, nx4);
    f2h_kernel<<<(np4 + 255) / 256, 256>>>(pw, p_ph, np4);
    gemm_h<<<dim3(M_TOK / 128, C_ / 128), 128, 57344>>>(p_ah, p_ph, pb,
                                                        out, M_TOK, C_, C_);
}

// round 16
// speedup vs baseline: 1.4727x; 1.4727x over previous
#include <cuda_runtime.h>
#include <cuda_fp16.h>
#include <cstdint>

#define B_ 16
#define L_ 680
#define C_ 1024
#define H_ 16
#define D_ 64
#define NSEG 10
#define M_TOK (B_*L_)          // 10880
#define SUMSQ 110468
#define LN100 4.605170185988091f

// ---------------- scratch -------------------------------------------------
__device__ float  g_qkv[(size_t)M_TOK * 3 * C_];
__device__ float  g_vt [(size_t)B_ * H_ * D_ * L_];
__device__ float  g_S  [(size_t)B_ * H_ * SUMSQ];
__device__ float  g_bias[3 * C_];
__device__ __half g_xh [(size_t)M_TOK * C_];
__device__ __half g_wh [(size_t)3 * C_ * C_];
__device__ __half g_ah [(size_t)M_TOK * C_];   // attention output, fp16 (proj input)
__device__ __half g_ph [(size_t)C_ * C_];

// ---------------- helpers --------------------------------------------------
__device__ __forceinline__ void mma16h(float* c, const uint32_t* a, const uint32_t* b) {
    asm volatile(
        "mma.sync.aligned.m16n8k16.row.col.f32.f16.f16.f32 "
        "{%0,%1,%2,%3}, {%4,%5,%6,%7}, {%8,%9}, {%0,%1,%2,%3};\n"
        : "+f"(c[0]), "+f"(c[1]), "+f"(c[2]), "+f"(c[3])
        : "r"(a[0]), "r"(a[1]), "r"(a[2]), "r"(a[3]), "r"(b[0]), "r"(b[1]));
}

__device__ __forceinline__ uint32_t smem_u32(const void* p) {
    return (uint32_t)__cvta_generic_to_shared(p);
}

__device__ __forceinline__ void cp16(uint32_t s, const void* g) {
    asm volatile("cp.async.cg.shared.global [%0], [%1], 16;\n" :: "r"(s), "l"(g));
}

__device__ __forceinline__ uint4 pack8h(float4 v0, float4 v1) {
    __half2 h0 = __floats2half2_rn(v0.x, v0.y);
    __half2 h1 = __floats2half2_rn(v0.z, v0.w);
    __half2 h2 = __floats2half2_rn(v1.x, v1.y);
    __half2 h3 = __floats2half2_rn(v1.z, v1.w);
    uint4 u;
    u.x = *(uint32_t*)&h0; u.y = *(uint32_t*)&h1;
    u.z = *(uint32_t*)&h2; u.w = *(uint32_t*)&h3;
    return u;
}

// ---------------- fp32 -> fp16 convert ------------------------------------
__global__ void f2h_kernel(const float* __restrict__ src, __half* __restrict__ dst,
                           int n4) {
    int i = blockIdx.x * blockDim.x + threadIdx.x;
    if (i >= n4) return;
    float4 v = *(const float4*)(src + (size_t)i * 4);
    __half2 lo = __floats2half2_rn(v.x, v.y);
    __half2 hi = __floats2half2_rn(v.z, v.w);
    *(__half2*)(dst + (size_t)i * 4)     = lo;
    *(__half2*)(dst + (size_t)i * 4 + 2) = hi;
}

// ---------------- bias assembly -------------------------------------------
__global__ void build_bias(const float* __restrict__ qb, const float* __restrict__ vb) {
    int j = blockIdx.x * blockDim.x + threadIdx.x;
    if (j >= 3 * C_) return;
    float v = 0.0f;
    if (j < C_) v = qb[j];
    else if (j >= 2 * C_) v = vb[j - 2 * C_];
    g_bias[j] = v;
}

// ========= cp.async fp16 GEMM: CTA 128x128, 4 warps of 64x64, 2 CTAs/SM ====
#define SROWH 56
#define BUFH (128 * SROWH)
__global__ __launch_bounds__(128, 2) void gemm_h(
    const __half* __restrict__ A, const __half* __restrict__ Bm,
    const float* __restrict__ bias, float* __restrict__ Cmat,
    int M, int N, int K)
{
    extern __shared__ __half smh[];

    const int tid  = threadIdx.x;
    const int lane = tid & 31, warp = tid >> 5;
    const int wm = warp & 1, wn = warp >> 1;
    const int qr = lane >> 2, qc = lane & 3;
    const int bm = blockIdx.x * 128, bn = blockIdx.y * 128;

    const int rr0 = tid >> 2;
    const int ch  = (tid & 3) << 3;

    float acc[4][8][4];
#pragma unroll
    for (int i = 0; i < 4; i++)
#pragma unroll
        for (int j = 0; j < 8; j++)
#pragma unroll
            for (int e = 0; e < 4; e++) acc[i][j][e] = 0.0f;

    const int nk = K >> 5;

    {
        __half* As = smh;
        __half* Bs = smh + BUFH;
#pragma unroll
        for (int i = 0; i < 4; i++) {
            int r = rr0 + 32 * i;
            cp16(smem_u32(As + r * SROWH + ch), A  + (size_t)(bm + r) * K + ch);
            cp16(smem_u32(Bs + r * SROWH + ch), Bm + (size_t)(bn + r) * K + ch);
        }
        asm volatile("cp.async.commit_group;\n");
    }

    for (int kt = 0; kt < nk; kt++) {
        asm volatile("cp.async.wait_group 0;\n");
        __syncthreads();

        if (kt + 1 < nk) {
            __half* As = smh + ((kt + 1) & 1) * 2 * BUFH;
            __half* Bs = As + BUFH;
            int ko = (kt + 1) << 5;
#pragma unroll
            for (int i = 0; i < 4; i++) {
                int r = rr0 + 32 * i;
                cp16(smem_u32(As + r * SROWH + ch), A  + (size_t)(bm + r) * K + ko + ch);
                cp16(smem_u32(Bs + r * SROWH + ch), Bm + (size_t)(bn + r) * K + ko + ch);
            }
            asm volatile("cp.async.commit_group;\n");
        }

        const __half* As = smh + (kt & 1) * 2 * BUFH;
        const __half* Bs = As + BUFH;

#pragma unroll
        for (int ks = 0; ks < 2; ks++) {
            const int cb = ks * 16 + qc * 2;
            uint32_t a[4][4], b[8][2];
#pragma unroll
            for (int mt = 0; mt < 4; mt++) {
                int row = wm * 64 + mt * 16 + qr;
                a[mt][0] = *(const uint32_t*)&As[row * SROWH + cb];
                a[mt][1] = *(const uint32_t*)&As[(row + 8) * SROWH + cb];
                a[mt][2] = *(const uint32_t*)&As[row * SROWH + cb + 8];
                a[mt][3] = *(const uint32_t*)&As[(row + 8) * SROWH + cb + 8];
            }
#pragma unroll
            for (int nt = 0; nt < 8; nt++) {
                int row = wn * 64 + nt * 8 + qr;
                b[nt][0] = *(const uint32_t*)&Bs[row * SROWH + cb];
                b[nt][1] = *(const uint32_t*)&Bs[row * SROWH + cb + 8];
            }
#pragma unroll
            for (int mt = 0; mt < 4; mt++)
#pragma unroll
                for (int nt = 0; nt < 8; nt++)
                    mma16h(acc[mt][nt], a[mt], b[nt]);
        }
        __syncthreads();
    }

#pragma unroll
    for (int mt = 0; mt < 4; mt++)
#pragma unroll
        for (int nt = 0; nt < 8; nt++) {
            int r = bm + wm * 64 + mt * 16 + qr;
            int c0 = bn + wn * 64 + nt * 8 + qc * 2;
            float b0 = bias[c0], b1 = bias[c0 + 1];
            Cmat[(size_t)r * N + c0]           = acc[mt][nt][0] + b0;
            Cmat[(size_t)r * N + c0 + 1]       = acc[mt][nt][1] + b1;
            Cmat[(size_t)(r + 8) * N + c0]     = acc[mt][nt][2] + b0;
            Cmat[(size_t)(r + 8) * N + c0 + 1] = acc[mt][nt][3] + b1;
        }
}

// ---------------- l2 normalize q (with scale) and k ------------------------
__global__ void normalize_qk(const float* __restrict__ scale_log) {
    int w = (blockIdx.x * blockDim.x + threadIdx.x) >> 5;
    int lane = threadIdx.x & 31;
    if (w >= M_TOK * H_) return;
    int t = w >> 4, h = w & 15;
    float sc = __expf(fminf(scale_log[h], LN100));

    float* q = g_qkv + ((size_t)t * 3 + 0) * C_ + h * D_;
    float* k = g_qkv + ((size_t)t * 3 + 1) * C_ + h * D_;

    float q0 = q[lane], q1 = q[lane + 32];
    float s = q0 * q0 + q1 * q1;
#pragma unroll
    for (int o = 16; o; o >>= 1) s += __shfl_xor_sync(~0u, s, o);
    float inv = sc / fmaxf(sqrtf(s), 1e-12f);
    q[lane] = q0 * inv; q[lane + 32] = q1 * inv;

    float k0 = k[lane], k1 = k[lane + 32];
    float sk = k0 * k0 + k1 * k1;
#pragma unroll
    for (int o = 16; o; o >>= 1) sk += __shfl_xor_sync(~0u, sk, o);
    float invk = 1.0f / fmaxf(sqrtf(sk), 1e-12f);
    k[lane] = k0 * invk; k[lane + 32] = k1 * invk;
}

// ---------------- V transpose ----------------------------------------------
__global__ void transpose_v() {
    __shared__ float tile[32][65];
    int bh = blockIdx.x;
    int l0 = blockIdx.y * 32;
    int b = bh >> 4, h = bh & 15;
    int tid = threadIdx.x;

    int d = tid & 63, lo = tid >> 6;
#pragma unroll
    for (int p = 0; p < 8; p++) {
        int l = l0 + p * 4 + lo;
        if (l < L_)
            tile[p * 4 + lo][d] = g_qkv[(((size_t)b * L_ + l) * 3 + 2) * C_ + h * D_ + d];
    }
    __syncthreads();

    int ll = tid & 31, d0 = tid >> 5;
#pragma unroll
    for (int p = 0; p < 8; p++) {
        int d2 = p * 8 + d0;
        int l = l0 + ll;
        if (l < L_)
            g_vt[((size_t)bh * D_ + d2) * L_ + l] = tile[ll][d2];
    }
}

// ---------------- S = Q @ K^T per (bh, segment), fp16 mma -------------------
// dyn smem: Ks half[256][72] (36864B) + Qs half[64][72] (9216B) = 46080 B
__global__ __launch_bounds__(256) void attn_s(const int* __restrict__ pn) {
    extern __shared__ __half smha[];
    __half (*Ks)[72] = (__half(*)[72])smha;
    __half (*Qs)[72] = (__half(*)[72])(smha + 256 * 72);

    int bh = blockIdx.x, seg = blockIdx.y;
    int b = bh >> 4, h = bh & 15;
    int start = 0, sqb = 0, ln = 0;
    for (int s = 0; s < NSEG; s++) {
        int p = pn[s];
        if (s == seg) { ln = p; break; }
        start += p; sqb += p * p;
    }
    int tid = threadIdx.x, lane = tid & 31, warp = tid >> 5;
    int qr = lane >> 2, qc = lane & 3;
    int nk = (ln + 7) & ~7;

    const float* Kg = g_qkv + (((size_t)b * L_ + start) * 3 + 1) * C_ + h * D_;
    for (int f = tid; f < nk * 8; f += 256) {
        int r = f >> 3, c8 = (f & 7) << 3;
        if (r < ln) {
            const float* p = Kg + (size_t)r * 3 * C_ + c8;
            *(uint4*)&Ks[r][c8] = pack8h(*(const float4*)p, *(const float4*)(p + 4));
        } else {
            *(uint4*)&Ks[r][c8] = make_uint4(0, 0, 0, 0);
        }
    }

    const float* Qg = g_qkv + (((size_t)b * L_ + start) * 3 + 0) * C_ + h * D_;
    float* Sg = g_S + (size_t)bh * SUMSQ + sqb;
    int Ntile = nk >> 3;

    for (int m0 = 0; m0 < ln; m0 += 64) {
        __syncthreads();
        int prows = min(64, (ln - m0 + 15) & ~15);
        for (int f = tid; f < prows * 8; f += 256) {
            int r = f >> 3, c8 = (f & 7) << 3;
            int gi = m0 + r;
            if (gi < ln) {
                const float* p = Qg + (size_t)gi * 3 * C_ + c8;
                *(uint4*)&Qs[r][c8] = pack8h(*(const float4*)p, *(const float4*)(p + 4));
            } else {
                *(uint4*)&Qs[r][c8] = make_uint4(0, 0, 0, 0);
            }
        }
        __syncthreads();

        int Mtile = prows >> 4;
        for (int t = warp; t < Mtile * Ntile; t += 8) {
            int mi = t / Ntile, ni = t % Ntile;
            float acc[4] = {0.f, 0.f, 0.f, 0.f};
            int row = mi * 16 + qr;
            int jr = ni * 8 + qr;
#pragma unroll
            for (int ks = 0; ks < 4; ks++) {
                const int cb = ks * 16 + qc * 2;
                uint32_t a[4], bf[2];
                a[0] = *(const uint32_t*)&Qs[row][cb];
                a[1] = *(const uint32_t*)&Qs[row + 8][cb];
                a[2] = *(const uint32_t*)&Qs[row][cb + 8];
                a[3] = *(const uint32_t*)&Qs[row + 8][cb + 8];
                bf[0] = *(const uint32_t*)&Ks[jr][cb];
                bf[1] = *(const uint32_t*)&Ks[jr][cb + 8];
                mma16h(acc, a, bf);
            }
            int i0 = m0 + row;
            int j0 = ni * 8 + qc * 2;
            if (i0 < ln) {
                if (j0 < ln)     Sg[(size_t)i0 * ln + j0]     = acc[0];
                if (j0 + 1 < ln) Sg[(size_t)i0 * ln + j0 + 1] = acc[1];
            }
            if (i0 + 8 < ln) {
                if (j0 < ln)     Sg[(size_t)(i0 + 8) * ln + j0]     = acc[2];
                if (j0 + 1 < ln) Sg[(size_t)(i0 + 8) * ln + j0 + 1] = acc[3];
            }
        }
    }
}

// ---------- O = softmax(S) @ V, softmax fused, fp16 mma, fp16 output -------
// dyn smem: Vt half[64][264] (33792B) + Ps u32[32][260] (33280B)
//           + Ph half[32][264] (16896B) = 83968 B  (2 CTAs/SM)
__global__ __launch_bounds__(256) void attn_o(const int* __restrict__ pn) {
    extern __shared__ char smo[];
    __half   (*Vt)[264] = (__half(*)[264])smo;
    uint32_t (*Ps)[260] = (uint32_t(*)[260])(smo + 33792);
    __half   (*Ph)[264] = (__half(*)[264])(smo + 33792 + 33280);

    int bh = blockIdx.x, seg = blockIdx.y;
    int b = bh >> 4, h = bh & 15;
    int start = 0, sqb = 0, ln = 0;
    for (int s = 0; s < NSEG; s++) {
        int p = pn[s];
        if (s == seg) { ln = p; break; }
        start += p; sqb += p * p;
    }
    int tid = threadIdx.x, lane = tid & 31, warp = tid >> 5;
    int qr = lane >> 2, qc = lane & 3;
    int nk16 = (ln + 15) & ~15;
    int Ksteps = nk16 >> 4;

    const float* Vg = g_vt + (size_t)bh * D_ * L_;
    for (int f = tid; f < 64 * nk16; f += 256) {
        int d = f / nk16, j = f % nk16;
        Vt[d][j] = (j < ln) ? __float2half(Vg[(size_t)d * L_ + start + j])
                            : __half(0.0f);
    }

    const float* Sg = g_S + (size_t)bh * SUMSQ + sqb;

    for (int m0 = 0; m0 < ln; m0 += 32) {
        __syncthreads();
        int prows = min(32, (ln - m0 + 15) & ~15);
        for (int f = tid; f < prows * nk16; f += 256) {
            int r = f / nk16, j = f % nk16;
            int gi = m0 + r;
            Ps[r][j < 260 ? j : 259] = (gi < ln && j < ln)
                       ? __float_as_uint(Sg[(size_t)gi * ln + j]) : 0u;
        }
        __syncthreads();

        for (int rr = warp; rr < prows; rr += 8) {
            float v[8];
            int cnt = 0;
            float m = -3.4e38f;
            for (int j = lane; j < ln; j += 32) {
                v[cnt] = __uint_as_float(Ps[rr][j]);
                m = fmaxf(m, v[cnt]); cnt++;
            }
#pragma unroll
            for (int o = 16; o; o >>= 1) m = fmaxf(m, __shfl_xor_sync(~0u, m, o));
            float s = 0.0f;
            for (int u = 0; u < cnt; u++) { v[u] = __expf(v[u] - m); s += v[u]; }
#pragma unroll
            for (int o = 16; o; o >>= 1) s += __shfl_xor_sync(~0u, s, o);
            float inv = 1.0f / s;
            cnt = 0;
            for (int j = lane; j < ln; j += 32) {
                Ph[rr][j] = __float2half(v[cnt] * inv); cnt++;
            }
            for (int j = ln + lane; j < nk16; j += 32)
                Ph[rr][j] = __half(0.0f);
        }
        __syncthreads();

        int Mtile = prows >> 4;
        for (int t = warp; t < Mtile * 8; t += 8) {
            int mi = t >> 3, ni = t & 7;
            float acc[4] = {0.f, 0.f, 0.f, 0.f};
            int row = mi * 16 + qr;
            int dr = ni * 8 + qr;
            for (int ks = 0; ks < Ksteps; ks++) {
                const int cb = ks * 16 + qc * 2;
                uint32_t a[4], bf[2];
                a[0] = *(const uint32_t*)&Ph[row][cb];
                a[1] = *(const uint32_t*)&Ph[row + 8][cb];
                a[2] = *(const uint32_t*)&Ph[row][cb + 8];
                a[3] = *(const uint32_t*)&Ph[row + 8][cb + 8];
                bf[0] = *(const uint32_t*)&Vt[dr][cb];
                bf[1] = *(const uint32_t*)&Vt[dr][cb + 8];
                mma16h(acc, a, bf);
            }
            int i0 = m0 + row;
            int c0 = ni * 8 + qc * 2;
            if (i0 < ln) {
                size_t o = ((size_t)b * L_ + start + i0) * C_ + h * D_ + c0;
                __half2 hv = __floats2half2_rn(acc[0], acc[1]);
                *(__half2*)(g_ah + o) = hv;
            }
            if (i0 + 8 < ln) {
                size_t o = ((size_t)b * L_ + start + i0 + 8) * C_ + h * D_ + c0;
                __half2 hv = __floats2half2_rn(acc[2], acc[3]);
                *(__half2*)(g_ah + o) = hv;
            }
        }
    }
}

// ---------------- launch ---------------------------------------------------
extern "C" void kernel_launch(void* const* d_in, const int* in_sizes, int n_in,
                              void* d_out, int out_size) {
    const float* x    = (const float*)d_in[0];
    const int*   pn   = (const int*)  d_in[1];
    const float* wqkv = (const float*)d_in[2];
    const float* qb   = (const float*)d_in[3];
    const float* vb   = (const float*)d_in[4];
    const float* slog = (const float*)d_in[5];
    const float* pw   = (const float*)d_in[6];
    const float* pb   = (const float*)d_in[7];
    float* out = (float*)d_out;

    float *p_qkv, *p_bias;
    __half *p_xh, *p_wh, *p_ah, *p_ph;
    cudaGetSymbolAddress((void**)&p_qkv,  g_qkv);
    cudaGetSymbolAddress((void**)&p_bias, g_bias);
    cudaGetSymbolAddress((void**)&p_xh,   g_xh);
    cudaGetSymbolAddress((void**)&p_wh,   g_wh);
    cudaGetSymbolAddress((void**)&p_ah,   g_ah);
    cudaGetSymbolAddress((void**)&p_ph,   g_ph);

    cudaFuncSetAttribute(gemm_h, cudaFuncAttributeMaxDynamicSharedMemorySize, 57344);
    cudaFuncSetAttribute(attn_s, cudaFuncAttributeMaxDynamicSharedMemorySize, 46080);
    cudaFuncSetAttribute(attn_o, cudaFuncAttributeMaxDynamicSharedMemorySize, 83968);

    const int nx4 = M_TOK * C_ / 4, nw4 = 3 * C_ * C_ / 4, np4 = C_ * C_ / 4;

    build_bias<<<12, 256>>>(qb, vb);
    f2h_kernel<<<(nx4 + 255) / 256, 256>>>(x, p_xh, nx4);
    f2h_kernel<<<(nw4 + 255) / 256, 256>>>(wqkv, p_wh, nw4);
    gemm_h<<<dim3(M_TOK / 128, (3 * C_) / 128), 128, 57344>>>(p_xh, p_wh, p_bias,
                                                              p_qkv, M_TOK, 3 * C_, C_);
    normalize_qk<<<(M_TOK * H_) / 8, 256>>>(slog);
    transpose_v<<<dim3(B_ * H_, (L_ + 31) / 32), 256>>>();
    attn_s<<<dim3(B_ * H_, NSEG), 256, 46080>>>(pn);
    attn_o<<<dim3(B_ * H_, NSEG), 256, 83968>>>(pn);
    f2h_kernel<<<(np4 + 255) / 256, 256>>>(pw, p_ph, np4);
    gemm_h<<<dim3(M_TOK / 128, C_ / 128), 128, 57344>>>(p_ah, p_ph, pb,
                                                        out, M_TOK, C_, C_);
}